// round 10
// baseline (speedup 1.0000x reference)
#include <cuda_runtime.h>

#define NN 50000
#define EE 800000
#define DD 64

// ---- scratch (static __device__) ----
__device__ float g_ex[EE];                   // exp(score) per edge
__device__ float g_segsum[NN];               // sum of ex per dst node
__device__ float g_accum[(size_t)NN * DD];   // sum of ex*value per node (unnormalized)

// 16-lane segmented reduction (edges/nodes packed 2 per warp)
__device__ __forceinline__ float wsum16(float v) {
#pragma unroll
    for (int o = 8; o; o >>= 1) v += __shfl_xor_sync(0xffffffffu, v, o);
    return v;
}

__global__ void init_kernel() {
    int i = blockIdx.x * blockDim.x + threadIdx.x;
    int stride = gridDim.x * blockDim.x;
    float4 z = make_float4(0.f, 0.f, 0.f, 0.f);
    for (int j = i; j < NN * DD / 4; j += stride) ((float4*)g_accum)[j] = z;
    for (int j = i; j < NN; j += stride) g_segsum[j] = 0.f;
}

// Two edges per warp; 16-lane group per edge, float4 per lane (4 dims).
// ALL 13 global loads (12 weight tensors + query) are issued up front so the
// DRAM pipe stays full across the shuffle-reduction phases (MLP_p1 ~ 13).
// Single fused pass: key -> score -> ex = exp(score) (no max-subtraction:
// |score| ~ N(0,64), far below exp overflow), value -> direct float4 atomic
// reduction into the node accumulator. No value staging to HBM.
__global__ void __launch_bounds__(256) edge_kernel(
    const float* __restrict__ feat, const float* __restrict__ query,
    const int* __restrict__ src, const int* __restrict__ dst,
    const float* __restrict__ skw, const float* __restrict__ skb,
    const float* __restrict__ dkw, const float* __restrict__ dkb,
    const float* __restrict__ ekw, const float* __restrict__ ekb,
    const float* __restrict__ svw, const float* __restrict__ svb,
    const float* __restrict__ dvw, const float* __restrict__ dvb,
    const float* __restrict__ evw, const float* __restrict__ evb,
    const float* __restrict__ kgamma, const float* __restrict__ kbeta,
    const float* __restrict__ vgamma, const float* __restrict__ vbeta)
{
    int pair = blockIdx.x * 8 + (threadIdx.x >> 5);   // warp id -> edge pair
    int lane = threadIdx.x & 31;
    int e = pair * 2 + (lane >> 4);                   // EE is even
    if (e >= EE) return;
    int d0 = (lane & 15) * 4;
    int s = src[e], t = dst[e];

    size_t base = (size_t)e * DD + d0;

    // -------- issue every global load up front (13 independent LDG.128) ------
    float4 u  = *(const float4*)(feat + (size_t)s * DD + d0);   // L2-resident
    float4 v  = *(const float4*)(feat + (size_t)t * DD + d0);
    float4 q  = *(const float4*)(query + (size_t)t * DD + d0);
    float4 kw1 = __ldcs((const float4*)(skw + base)), kb1 = __ldcs((const float4*)(skb + base));
    float4 kw2 = __ldcs((const float4*)(dkw + base)), kb2 = __ldcs((const float4*)(dkb + base));
    float4 kw3 = __ldcs((const float4*)(ekw + base)), kb3 = __ldcs((const float4*)(ekb + base));
    float4 vw1 = __ldcs((const float4*)(svw + base)), vb1 = __ldcs((const float4*)(svb + base));
    float4 vw2 = __ldcs((const float4*)(dvw + base)), vb2 = __ldcs((const float4*)(dvb + base));
    float4 vw3 = __ldcs((const float4*)(evw + base)), vb3 = __ldcs((const float4*)(evb + base));

    // ---------------- key branch -> score -> ex ----------------
    float ex;
    {
        float h0 = fmaf(u.x, kw1.x, kb1.x) + fmaf(v.x, kw2.x, kb2.x);
        float h1 = fmaf(u.y, kw1.y, kb1.y) + fmaf(v.y, kw2.y, kb2.y);
        float h2 = fmaf(u.z, kw1.z, kb1.z) + fmaf(v.z, kw2.z, kb2.z);
        float h3 = fmaf(u.w, kw1.w, kb1.w) + fmaf(v.w, kw2.w, kb2.w);
        h0 = fmaf(fmaxf(h0, 0.f), kw3.x, kb3.x);
        h1 = fmaf(fmaxf(h1, 0.f), kw3.y, kb3.y);
        h2 = fmaf(fmaxf(h2, 0.f), kw3.z, kb3.z);
        h3 = fmaf(fmaxf(h3, 0.f), kw3.w, kb3.w);
        float mu  = wsum16(h0 + h1 + h2 + h3) * (1.f / DD);
        float d_0 = h0 - mu, d_1 = h1 - mu, d_2 = h2 - mu, d_3 = h3 - mu;
        float var = wsum16(d_0 * d_0 + d_1 * d_1 + d_2 * d_2 + d_3 * d_3) * (1.f / DD);
        float inv = rsqrtf(var + 1e-5f);
        float4 g  = *(const float4*)(kgamma + d0);
        float4 bb = *(const float4*)(kbeta + d0);
        float k0 = fmaf(d_0 * inv, g.x, bb.x);
        float k1 = fmaf(d_1 * inv, g.y, bb.y);
        float k2 = fmaf(d_2 * inv, g.z, bb.z);
        float k3 = fmaf(d_3 * inv, g.w, bb.w);
        float sc = wsum16(k0 * q.x + k1 * q.y + k2 * q.z + k3 * q.w);
        ex = expf(sc);                                 // all 16 lanes hold ex
        if ((lane & 15) == 0) {
            g_ex[e] = ex;
            atomicAdd(&g_segsum[t], ex);
        }
    }

    // ---------------- value branch -> direct weighted reduction ----------------
    {
        float h0 = fmaf(u.x, vw1.x, vb1.x) + fmaf(v.x, vw2.x, vb2.x);
        float h1 = fmaf(u.y, vw1.y, vb1.y) + fmaf(v.y, vw2.y, vb2.y);
        float h2 = fmaf(u.z, vw1.z, vb1.z) + fmaf(v.z, vw2.z, vb2.z);
        float h3 = fmaf(u.w, vw1.w, vb1.w) + fmaf(v.w, vw2.w, vb2.w);
        h0 = fmaf(fmaxf(h0, 0.f), vw3.x, vb3.x);
        h1 = fmaf(fmaxf(h1, 0.f), vw3.y, vb3.y);
        h2 = fmaf(fmaxf(h2, 0.f), vw3.z, vb3.z);
        h3 = fmaf(fmaxf(h3, 0.f), vw3.w, vb3.w);
        float mu  = wsum16(h0 + h1 + h2 + h3) * (1.f / DD);
        float d_0 = h0 - mu, d_1 = h1 - mu, d_2 = h2 - mu, d_3 = h3 - mu;
        float var = wsum16(d_0 * d_0 + d_1 * d_1 + d_2 * d_2 + d_3 * d_3) * (1.f / DD);
        float inv = rsqrtf(var + 1e-5f);
        float4 g  = *(const float4*)(vgamma + d0);
        float4 bb = *(const float4*)(vbeta + d0);
        atomicAdd((float4*)(g_accum + (size_t)t * DD + d0),
                  make_float4(fmaf(d_0 * inv, g.x, bb.x) * ex,
                              fmaf(d_1 * inv, g.y, bb.y) * ex,
                              fmaf(d_2 * inv, g.z, bb.z) * ex,
                              fmaf(d_3 * inv, g.w, bb.w) * ex));
    }
}

// attn[e] = ex / segsum[dst]; 4 edges per thread (EE % 4 == 0)
__global__ void attn_kernel(const int* __restrict__ dst, float* __restrict__ attn_out) {
    int i = blockIdx.x * blockDim.x + threadIdx.x;
    if (i >= EE / 4) return;
    float4 ex = *(const float4*)(g_ex + (size_t)i * 4);
    int4 t = *(const int4*)(dst + (size_t)i * 4);
    *(float4*)(attn_out + (size_t)i * 4) =
        make_float4(ex.x / g_segsum[t.x], ex.y / g_segsum[t.y],
                    ex.z / g_segsum[t.z], ex.w / g_segsum[t.w]);
}

// Normalize by segsum, then LayerNorm; 2 nodes per warp, float4 per lane.
__global__ void __launch_bounds__(256) node_ln_kernel(const float* __restrict__ agamma,
                                                      const float* __restrict__ abeta,
                                                      float* __restrict__ out) {
    int w = blockIdx.x * 8 + (threadIdx.x >> 5);
    int lane = threadIdx.x & 31;
    int n = w * 2 + (lane >> 4);                       // NN is even
    if (n >= NN) return;
    int d0 = (lane & 15) * 4;
    float ssum = g_segsum[n];
    float inv_s = (ssum > 0.f) ? (1.f / ssum) : 0.f;
    float4 a = *(const float4*)(g_accum + (size_t)n * DD + d0);
    a.x *= inv_s; a.y *= inv_s; a.z *= inv_s; a.w *= inv_s;
    float mu  = wsum16(a.x + a.y + a.z + a.w) * (1.f / DD);
    float d_0 = a.x - mu, d_1 = a.y - mu, d_2 = a.z - mu, d_3 = a.w - mu;
    float var = wsum16(d_0 * d_0 + d_1 * d_1 + d_2 * d_2 + d_3 * d_3) * (1.f / DD);
    float inv = rsqrtf(var + 1e-5f);
    float4 g = *(const float4*)(agamma + d0);
    float4 b = *(const float4*)(abeta + d0);
    *(float4*)(out + (size_t)n * DD + d0) =
        make_float4(fmaf(d_0 * inv, g.x, b.x), fmaf(d_1 * inv, g.y, b.y),
                    fmaf(d_2 * inv, g.z, b.z), fmaf(d_3 * inv, g.w, b.w));
}

extern "C" void kernel_launch(void* const* d_in, const int* in_sizes, int n_in,
                              void* d_out, int out_size) {
    const float* feat  = (const float*)d_in[0];
    const float* query = (const float*)d_in[1];
    const int*   src   = (const int*)d_in[2];
    const int*   dst   = (const int*)d_in[3];
    const float* skw = (const float*)d_in[4],  *skb = (const float*)d_in[5];
    const float* dkw = (const float*)d_in[6],  *dkb = (const float*)d_in[7];
    const float* ekw = (const float*)d_in[8],  *ekb = (const float*)d_in[9];
    const float* svw = (const float*)d_in[10], *svb = (const float*)d_in[11];
    const float* dvw = (const float*)d_in[12], *dvb = (const float*)d_in[13];
    const float* evw = (const float*)d_in[14], *evb = (const float*)d_in[15];
    const float* kg  = (const float*)d_in[16], *kb  = (const float*)d_in[17];
    const float* vg  = (const float*)d_in[18], *vb  = (const float*)d_in[19];
    const float* ag  = (const float*)d_in[20], *ab  = (const float*)d_in[21];

    float* out  = (float*)d_out;                 // [N, D]
    float* attn = out + (size_t)NN * DD;         // [E, 1]

    init_kernel<<<1024, 256>>>();
    // 8 warps/block, 2 edges/warp -> 16 edges per block
    edge_kernel<<<(EE / 2 + 7) / 8, 256>>>(feat, query, src, dst,
                                           skw, skb, dkw, dkb, ekw, ekb,
                                           svw, svb, dvw, dvb, evw, evb,
                                           kg, kb, vg, vb);
    attn_kernel<<<(EE / 4 + 255) / 256, 256>>>(dst, attn);
    node_ln_kernel<<<(NN / 2 + 7) / 8, 256>>>(ag, ab, out);
}